// round 14
// baseline (speedup 1.0000x reference)
#include <cuda_runtime.h>
#include <cuda_bf16.h>
#include <math.h>
#include <cstdint>
#include <mma.h>

using namespace nvcuda;

// Problem constants
#define Bz 2
#define Tz 2048
#define Cz 1024
#define Hh 16
#define Dd 64
#define CH 512
#define NT (Bz*Tz)          // 4096 rows

// ---------------- scratch (device globals; no runtime alloc) ----------------
__device__ float g_Himp[NT*CH];
__device__ float g_xi[NT*Cz];
__device__ float g_Hrsn[NT*Cz];
__device__ float g_reasoned[NT*Cz];
__device__ float g_Q[NT*Cz];
__device__ float g_K[NT*Cz];
__device__ float g_V[NT*Cz];
__device__ float g_attn[NT*Cz];
__device__ float g_proj[NT*Cz];
__device__ float g_part[16*Cz];
__device__ float g_rmean[Bz*Cz];
__device__ float g_temp[Bz*Hh];
__device__ float g_xr[NT*Cz];          // x rounded to tf32
__device__ uint32_t g_mbits[(size_t)Bz*Tz*Tz/32];   // packed attention mask (1MB)
// transposed (N-major -> [N,K] K-contiguous) + tf32-rounded weights
__device__ float g_WtImp[CH*Cz];
__device__ float g_WtRsn1[Cz*Cz];
__device__ float g_WtRsn2[Cz*Cz];
__device__ float g_WtQ[Cz*Cz];
__device__ float g_WtK[Cz*Cz];
__device__ float g_WtV[Cz*Cz];
__device__ float g_WtO[Cz*Cz];

// ---------------- helpers ----------------
__device__ __forceinline__ uint32_t smem_to_u32(const void* p) {
    uint32_t a;
    asm("{ .reg .u64 t; cvta.to.shared.u64 t, %1; cvt.u32.u64 %0, t; }" : "=r"(a) : "l"(p));
    return a;
}
__device__ __forceinline__ float to_tf32(float f) {
    uint32_t u; asm("cvt.rna.tf32.f32 %0, %1;" : "=r"(u) : "f"(f));
    return __uint_as_float(u);
}
__device__ __forceinline__ void cp_async16(uint32_t dst, const void* src) {
    asm volatile("cp.async.cg.shared.global [%0], [%1], 16;" :: "r"(dst), "l"(src) : "memory");
}
__device__ __forceinline__ void cp_commit() { asm volatile("cp.async.commit_group;" ::: "memory"); }
template<int N> __device__ __forceinline__ void cp_wait() {
    asm volatile("cp.async.wait_group %0;" :: "n"(N) : "memory");
}

__device__ __forceinline__ float blockReduceSum(float v) {
    __shared__ float sh[32];
    int lane = threadIdx.x & 31, wid = threadIdx.x >> 5;
    #pragma unroll
    for (int o = 16; o; o >>= 1) v += __shfl_down_sync(0xffffffffu, v, o);
    if (lane == 0) sh[wid] = v;
    __syncthreads();
    int nw = blockDim.x >> 5;
    v = (threadIdx.x < nw) ? sh[threadIdx.x] : 0.f;
    if (wid == 0) {
        #pragma unroll
        for (int o = 16; o; o >>= 1) v += __shfl_down_sync(0xffffffffu, v, o);
        if (lane == 0) sh[0] = v;
    }
    __syncthreads();
    float r = sh[0];
    __syncthreads();
    return r;
}

__device__ __forceinline__ float gelu_exact(float x) {
    return 0.5f * x * (1.0f + erff(x * 0.70710678118654752f));
}

// ---------------- wmma tf32 GEMM core (3-stage cp.async pipeline, 512 threads) ----------------
// CTA tile 128x128, 16 warps in 4x4, warp tile 32x32 (2x2 frags).
#define GT   512
#define GLD  36
#define GSTG (128*GLD)
#define GSTAGE_FLOATS (2*GSTG)
#define GNSTAGE 3
#define GSMEM_BYTES (GNSTAGE*GSTAGE_FLOATS*4)    // 110592 B
#define ELD 132

__device__ __forceinline__ void gemm_tf32_body(
    float* smf, uint32_t sb,
    const float* __restrict__ A, const float* __restrict__ Wt,
    const float* __restrict__ bias, float* __restrict__ C,
    int N, int round_out, int bx, int by)
{
    const int tid = threadIdx.x;
    const int wid = tid >> 5;
    const int wm = wid >> 2;          // 0..3 (M dir, 32 rows each)
    const int wn = wid & 3;           // 0..3 (N dir, 32 cols each)

    wmma::fragment<wmma::accumulator, 16, 16, 8, float> acc[2][2];
    #pragma unroll
    for (int mi = 0; mi < 2; mi++)
        #pragma unroll
        for (int ni = 0; ni < 2; ni++)
            wmma::fill_fragment(acc[mi][ni], 0.0f);

    const float* Abase = A  + (size_t)by * 128 * Cz;
    const float* Bbase = Wt + (size_t)bx * 128 * Cz;

    auto load_stage = [&](int s, int kc) {
        uint32_t ab = sb + (uint32_t)s * GSTAGE_FLOATS * 4;
        uint32_t bb = ab + GSTG * 4;
        #pragma unroll
        for (int i = 0; i < 2; i++) {
            int idx = i * GT + tid;
            int r = idx >> 3, c = (idx & 7) * 4;
            uint32_t soff = (uint32_t)(r * GLD + c) * 4;
            cp_async16(ab + soff, Abase + (size_t)r * Cz + kc * 32 + c);
            cp_async16(bb + soff, Bbase + (size_t)r * Cz + kc * 32 + c);
        }
        cp_commit();
    };

    load_stage(0, 0);
    load_stage(1, 1);
    load_stage(2, 2);

    for (int kc = 0; kc < 32; kc++) {
        int s = kc % 3;
        if (kc < 30)       cp_wait<2>();
        else if (kc == 30) cp_wait<1>();
        else               cp_wait<0>();
        __syncthreads();

        const float* As = smf + s * GSTAGE_FLOATS;
        const float* Bs = As + GSTG;

        #pragma unroll
        for (int kk = 0; kk < 4; kk++) {
            wmma::fragment<wmma::matrix_a, 16, 16, 8, wmma::precision::tf32, wmma::row_major> af[2];
            wmma::fragment<wmma::matrix_b, 16, 16, 8, wmma::precision::tf32, wmma::col_major> bf[2];
            #pragma unroll
            for (int mi = 0; mi < 2; mi++)
                wmma::load_matrix_sync(af[mi], As + (wm * 32 + mi * 16) * GLD + kk * 8, GLD);
            #pragma unroll
            for (int ni = 0; ni < 2; ni++)
                wmma::load_matrix_sync(bf[ni], Bs + (wn * 32 + ni * 16) * GLD + kk * 8, GLD);
            #pragma unroll
            for (int mi = 0; mi < 2; mi++)
                #pragma unroll
                for (int ni = 0; ni < 2; ni++)
                    wmma::mma_sync(acc[mi][ni], af[mi], bf[ni], acc[mi][ni]);
        }
        __syncthreads();
        if (kc + 3 < 32) load_stage(s, kc + 3);
    }

    #pragma unroll
    for (int mi = 0; mi < 2; mi++)
        #pragma unroll
        for (int ni = 0; ni < 2; ni++)
            wmma::store_matrix_sync(smf + (wm * 32 + mi * 16) * ELD + wn * 32 + ni * 16,
                                    acc[mi][ni], ELD, wmma::mem_row_major);
    __syncthreads();

    #pragma unroll
    for (int i = 0; i < 8; i++) {
        int idx = i * GT + tid;
        int r = idx >> 5, c = (idx & 31) * 4;
        const float* bp = bias + bx * 128 + c;
        float4 o;
        o.x = smf[r * ELD + c + 0] + bp[0];
        o.y = smf[r * ELD + c + 1] + bp[1];
        o.z = smf[r * ELD + c + 2] + bp[2];
        o.w = smf[r * ELD + c + 3] + bp[3];
        if (round_out) {
            o.x = to_tf32(o.x); o.y = to_tf32(o.y);
            o.z = to_tf32(o.z); o.w = to_tf32(o.w);
        }
        *(float4*)&C[(size_t)(by * 128 + r) * N + bx * 128 + c] = o;
    }
}

__global__ __launch_bounds__(GT, 1) void gemm_tf32(
    const float* __restrict__ A, const float* __restrict__ Wt,
    const float* __restrict__ bias, float* __restrict__ C,
    int N, int round_out)
{
    extern __shared__ float smf[];
    gemm_tf32_body(smf, smem_to_u32(smf), A, Wt, bias, C, N, round_out,
                   blockIdx.x, blockIdx.y);
}

// batched Q/K/V: blockIdx.z selects (input, weight, bias, output); all N=Cz, rounded
__global__ __launch_bounds__(GT, 1) void gemm_tf32_qkv(
    const float* __restrict__ Aq, const float* __restrict__ Ak, const float* __restrict__ Av,
    const float* __restrict__ Wq, const float* __restrict__ Wk, const float* __restrict__ Wv,
    const float* __restrict__ bq, const float* __restrict__ bk, const float* __restrict__ bv,
    float* __restrict__ Cq, float* __restrict__ Ck, float* __restrict__ Cv)
{
    extern __shared__ float smf[];
    const float* A; const float* W; const float* bb; float* C;
    if (blockIdx.z == 0)      { A = Aq; W = Wq; bb = bq; C = Cq; }
    else if (blockIdx.z == 1) { A = Ak; W = Wk; bb = bk; C = Ck; }
    else                      { A = Av; W = Wv; bb = bv; C = Cv; }
    gemm_tf32_body(smf, smem_to_u32(smf), A, W, bb, C, Cz, 1,
                   blockIdx.x, blockIdx.y);
}

// ---------------- batched transpose + round: 7 weights in one launch ----------------
struct TransArgs {
    const float* src[7];
    float* dst[7];
    int n[7];           // N (output rows of Wt); K is always Cz
};

__global__ void transpose_round_batch(TransArgs ta) {
    int z = blockIdx.z;
    int N = ta.n[z];
    int nb = blockIdx.x * 32, kb = blockIdx.y * 32;
    if (nb >= N) return;
    const float* W = ta.src[z];
    float* Wt = ta.dst[z];
    __shared__ float t[32][33];
    #pragma unroll
    for (int i = threadIdx.y; i < 32; i += 8)
        t[i][threadIdx.x] = W[(size_t)(kb + i) * N + nb + threadIdx.x];
    __syncthreads();
    #pragma unroll
    for (int i = threadIdx.y; i < 32; i += 8)
        Wt[(size_t)(nb + i) * Cz + kb + threadIdx.x] = to_tf32(t[threadIdx.x][i]);
}

__global__ void round_tf32_kernel(const float* __restrict__ in, float* __restrict__ out) {
    int i = blockIdx.x * 256 + threadIdx.x;
    out[i] = to_tf32(in[i]);
}

// ---------------- pack mask to bits (ballot) ----------------
__global__ void pack_mask_kernel(const int* __restrict__ mask, uint32_t* __restrict__ mbits) {
    size_t p = (size_t)blockIdx.x * 256 + threadIdx.x;
    unsigned bit = (mask[p] != 0) ? 1u : 0u;
    uint32_t w = __ballot_sync(0xffffffffu, bit);
    if ((threadIdx.x & 31) == 0) mbits[p >> 5] = w;
}

// ---------------- LN + GELU ----------------
template<int COLS>
__global__ __launch_bounds__(256) void ln_gelu_kernel(
    float* __restrict__ X, const float* __restrict__ g, const float* __restrict__ beta)
{
    const int row = blockIdx.x;
    float* xr = X + (size_t)row * COLS;
    constexpr int PT = COLS / 256;
    float v[PT];
    float s = 0.f;
    #pragma unroll
    for (int i = 0; i < PT; i++) { v[i] = xr[threadIdx.x + i * 256]; s += v[i]; }
    float mean = blockReduceSum(s) * (1.0f / COLS);
    float s2 = 0.f;
    #pragma unroll
    for (int i = 0; i < PT; i++) { float d = v[i] - mean; s2 += d * d; }
    float var = blockReduceSum(s2) * (1.0f / COLS);
    float rstd = rsqrtf(var + 1e-5f);
    #pragma unroll
    for (int i = 0; i < PT; i++) {
        int c = threadIdx.x + i * 256;
        float y = (v[i] - mean) * rstd * g[c] + beta[c];
        xr[c] = to_tf32(gelu_exact(y));
    }
}

// ---------------- importance gate ----------------
__global__ __launch_bounds__(256) void gate_xi_kernel(
    const float* __restrict__ H, const float* __restrict__ w2, const float* __restrict__ b2,
    const float* __restrict__ x, float* __restrict__ xi)
{
    const int row = blockIdx.x;
    float p = 0.f;
    const float* hr = H + (size_t)row * CH;
    for (int c = threadIdx.x; c < CH; c += 256) p += hr[c] * w2[c];
    float sum = blockReduceSum(p);
    float sg = 1.0f / (1.0f + expf(-(sum + b2[0])));
    float imp = fmaxf(sg, 1e-6f);
    const float* xr = x + (size_t)row * Cz;
    float* xo = xi + (size_t)row * Cz;
    for (int c = threadIdx.x; c < Cz; c += 256) xo[c] = to_tf32(xr[c] * imp);
}

// ---------------- column mean ----------------
__global__ void colmean_part(const float* __restrict__ R, float* __restrict__ part) {
    int c = blockIdx.x * 256 + threadIdx.x;
    int b = blockIdx.y;
    int ch = blockIdx.z;
    float s = 0.f;
    int t0 = ch * 256;
    for (int t = t0; t < t0 + 256; t++)
        s += R[((size_t)(b * Tz + t)) * Cz + c];
    part[(ch * Bz + b) * Cz + c] = s;
}
__global__ void colmean_fin(const float* __restrict__ part, float* __restrict__ out) {
    int c = blockIdx.x * 256 + threadIdx.x;
    int b = blockIdx.y;
    float s = 0.f;
    for (int ch = 0; ch < 8; ch++) s += part[(ch * Bz + b) * Cz + c];
    out[b * Cz + c] = s * (1.0f / Tz);
}

// ---------------- temperature net ----------------
__global__ __launch_bounds__(512) void temp_kernel(
    const float* __restrict__ rmean,
    const float* __restrict__ w1, const float* __restrict__ b1,
    const float* __restrict__ g, const float* __restrict__ beta,
    const float* __restrict__ w2, const float* __restrict__ b2,
    float* __restrict__ temp)
{
    const int b = blockIdx.x;
    const int tid = threadIdx.x;
    __shared__ float hsm[CH];
    const float* xr = rmean + b * Cz;
    float acc = b1[tid];
    for (int k = 0; k < Cz; k++) acc = fmaf(xr[k], w1[k * CH + tid], acc);
    float mean = blockReduceSum(acc) * (1.0f / CH);
    float d = acc - mean;
    float var = blockReduceSum(d * d) * (1.0f / CH);
    float rstd = rsqrtf(var + 1e-5f);
    float y = d * rstd * g[tid] + beta[tid];
    hsm[tid] = gelu_exact(y);
    __syncthreads();
    if (tid < Hh) {
        float a2 = b2[tid];
        for (int k = 0; k < CH; k++) a2 = fmaf(hsm[k], w2[k * Hh + tid], a2);
        float sp = (a2 > 20.f) ? a2 : log1pf(expf(a2));
        temp[b * Hh + tid] = sp + 0.5f;
    }
}

// ---------------- wmma tf32 flash attention ----------------
#define AQS 0
#define AKS 8704
#define AVS 17408
#define ASS 25600
#define AOS 42496
#define AMS 51200
#define ALS 51328
#define ACS 51456
#define ASM_FLOATS 51584
#define ASM_BYTES (ASM_FLOATS*4)

__global__ __launch_bounds__(256) void flash_wmma_kernel(
    const float* __restrict__ Q, const float* __restrict__ Kp,
    const float* __restrict__ Vp, const uint32_t* __restrict__ mbits,
    const float* __restrict__ temp, float* __restrict__ O)
{
    extern __shared__ float smf[];
    uint32_t sb = smem_to_u32(smf);
    const int tid = threadIdx.x;
    const int wid = tid >> 5;
    const int wm = wid >> 2;          // 0..1
    const int wn = wid & 3;           // 0..3
    const int qt = blockIdx.x, h = blockIdx.y, b = blockIdx.z;
    const int qrow0 = qt * 128;
    const float sc = 0.125f * temp[b * Hh + h];

    #pragma unroll
    for (int i = 0; i < 8; i++) {
        int idx = i * 256 + tid;
        int r = idx >> 4, c4 = (idx & 15) * 4;
        float4 qv = *(const float4*)(Q + ((size_t)(b * Tz + qrow0 + r)) * Cz + h * Dd + c4);
        *(float4*)&smf[AQS + r * 68 + c4] = qv;
    }
    if (tid < 128) { smf[AMS + tid] = -1e30f; smf[ALS + tid] = 0.f; }

    auto load_K = [&](int k0) {
        #pragma unroll
        for (int i = 0; i < 8; i++) {
            int idx = i * 256 + tid;
            int r = idx >> 4, c4 = (idx & 15) * 4;
            cp_async16(sb + (AKS + r * 68 + c4) * 4,
                       Kp + ((size_t)(b * Tz + k0 + r)) * Cz + h * Dd + c4);
        }
        cp_commit();
    };
    auto load_V = [&](int k0) {
        #pragma unroll
        for (int i = 0; i < 8; i++) {
            int idx = i * 256 + tid;
            int r = idx >> 4, c4 = (idx & 15) * 4;
            cp_async16(sb + (AVS + r * 64 + c4) * 4,
                       Vp + ((size_t)(b * Tz + k0 + r)) * Cz + h * Dd + c4);
        }
        cp_commit();
    };

    load_K(0);
    load_V(0);
    __syncthreads();

    const int NBLK = Tz / 128;   // 16
    for (int blk = 0; blk < NBLK; blk++) {
        int k0 = blk * 128;
        cp_wait<1>();
        __syncthreads();

        // ---- S = Q @ K^T ----
        {
            wmma::fragment<wmma::accumulator, 16, 16, 8, float> acc[4][2];
            #pragma unroll
            for (int mi = 0; mi < 4; mi++)
                #pragma unroll
                for (int ni = 0; ni < 2; ni++)
                    wmma::fill_fragment(acc[mi][ni], 0.0f);
            #pragma unroll
            for (int kk = 0; kk < 8; kk++) {
                wmma::fragment<wmma::matrix_a, 16, 16, 8, wmma::precision::tf32, wmma::row_major> af[4];
                wmma::fragment<wmma::matrix_b, 16, 16, 8, wmma::precision::tf32, wmma::col_major> bf[2];
                #pragma unroll
                for (int mi = 0; mi < 4; mi++)
                    wmma::load_matrix_sync(af[mi], smf + AQS + (wm * 64 + mi * 16) * 68 + kk * 8, 68);
                #pragma unroll
                for (int ni = 0; ni < 2; ni++)
                    wmma::load_matrix_sync(bf[ni], smf + AKS + (wn * 32 + ni * 16) * 68 + kk * 8, 68);
                #pragma unroll
                for (int mi = 0; mi < 4; mi++)
                    #pragma unroll
                    for (int ni = 0; ni < 2; ni++)
                        wmma::mma_sync(acc[mi][ni], af[mi], bf[ni], acc[mi][ni]);
            }
            #pragma unroll
            for (int mi = 0; mi < 4; mi++)
                #pragma unroll
                for (int ni = 0; ni < 2; ni++)
                    wmma::store_matrix_sync(smf + ASS + (wm * 64 + mi * 16) * 132 + wn * 32 + ni * 16,
                                            acc[mi][ni], 132, wmma::mem_row_major);
        }
        __syncthreads();

        if (blk + 1 < NBLK) load_K(k0 + 128);

        // ---- online softmax ----
        {
            int r = tid >> 1, c0 = (tid & 1) * 64;
            size_t mb_idx = (((size_t)(b * Tz + qrow0 + r)) * Tz + k0 + c0) >> 5;
            uint32_t w0 = mbits[mb_idx], w1 = mbits[mb_idx + 1];
            uint64_t mw = (uint64_t)w0 | ((uint64_t)w1 << 32);
            float* Srow = smf + ASS + r * 132 + c0;
            float vmax = -1e30f;
            #pragma unroll
            for (int j = 0; j < 64; j++) {
                float s = Srow[j];
                s = ((mw >> j) & 1ull) ? s * sc : -1e30f;
                Srow[j] = s;
                vmax = fmaxf(vmax, s);
            }
            vmax = fmaxf(vmax, __shfl_xor_sync(0xffffffffu, vmax, 1));
            float mold = smf[AMS + r];
            float mnew = fmaxf(mold, vmax);
            float corr = __expf(mold - mnew);
            float lsum = 0.f;
            #pragma unroll
            for (int j = 0; j < 64; j++) {
                float p = __expf(Srow[j] - mnew);
                lsum += p;
                Srow[j] = to_tf32(p);
            }
            lsum += __shfl_xor_sync(0xffffffffu, lsum, 1);
            if ((tid & 1) == 0) {
                smf[AMS + r] = mnew;
                smf[ALS + r] = smf[ALS + r] * corr + lsum;
                smf[ACS + r] = corr;
            }
        }

        if (blk + 1 < NBLK) cp_wait<1>(); else cp_wait<0>();
        __syncthreads();

        // ---- PV = P @ V ----
        {
            wmma::fragment<wmma::accumulator, 16, 16, 8, float> acc2[4];
            #pragma unroll
            for (int mi = 0; mi < 4; mi++) wmma::fill_fragment(acc2[mi], 0.0f);
            #pragma unroll
            for (int kk = 0; kk < 16; kk++) {
                wmma::fragment<wmma::matrix_b, 16, 16, 8, wmma::precision::tf32, wmma::row_major> bf;
                wmma::load_matrix_sync(bf, smf + AVS + (kk * 8) * 64 + wn * 16, 64);
                #pragma unroll
                for (int mi = 0; mi < 4; mi++) {
                    wmma::fragment<wmma::matrix_a, 16, 16, 8, wmma::precision::tf32, wmma::row_major> af;
                    wmma::load_matrix_sync(af, smf + ASS + (wm * 64 + mi * 16) * 132 + kk * 8, 132);
                    wmma::mma_sync(acc2[mi], af, bf, acc2[mi]);
                }
            }
            __syncthreads();
            #pragma unroll
            for (int mi = 0; mi < 4; mi++)
                wmma::store_matrix_sync(smf + ASS + (wm * 64 + mi * 16) * 132 + wn * 16,
                                        acc2[mi], 132, wmma::mem_row_major);
        }

        if (blk + 1 < NBLK) load_V(k0 + 128);
        __syncthreads();

        // ---- merge into O ----
        if (blk == 0) {
            #pragma unroll
            for (int i = 0; i < 32; i++) {
                int idx = i * 256 + tid;
                int r = idx >> 6, c = idx & 63;
                smf[AOS + r * 68 + c] = smf[ASS + r * 132 + c];
            }
        } else {
            #pragma unroll
            for (int i = 0; i < 32; i++) {
                int idx = i * 256 + tid;
                int r = idx >> 6, c = idx & 63;
                smf[AOS + r * 68 + c] = smf[AOS + r * 68 + c] * smf[ACS + r] + smf[ASS + r * 132 + c];
            }
        }
        __syncthreads();
    }

    #pragma unroll
    for (int i = 0; i < 32; i++) {
        int idx = i * 256 + tid;
        int r = idx >> 6, c = idx & 63;
        float val = smf[AOS + r * 68 + c] / smf[ALS + r];
        O[((size_t)(b * Tz + qrow0 + r)) * Cz + h * Dd + c] = to_tf32(val);
    }
}

// ---------------- residual + LayerNorm epilogue ----------------
__global__ __launch_bounds__(256) void resid_ln_kernel(
    const float* __restrict__ x, const float* __restrict__ p,
    const float* __restrict__ g, const float* __restrict__ beta,
    float* __restrict__ out)
{
    const int row = blockIdx.x;
    const float* xr = x + (size_t)row * Cz;
    const float* pr = p + (size_t)row * Cz;
    float v[4];
    float s = 0.f;
    #pragma unroll
    for (int i = 0; i < 4; i++) {
        int c = threadIdx.x + i * 256;
        v[i] = xr[c] + pr[c];
        s += v[i];
    }
    float mean = blockReduceSum(s) * (1.0f / Cz);
    float s2 = 0.f;
    #pragma unroll
    for (int i = 0; i < 4; i++) { float d = v[i] - mean; s2 += d * d; }
    float var = blockReduceSum(s2) * (1.0f / Cz);
    float rstd = rsqrtf(var + 1e-5f);
    #pragma unroll
    for (int i = 0; i < 4; i++) {
        int c = threadIdx.x + i * 256;
        out[(size_t)row * Cz + c] = (v[i] - mean) * rstd * g[c] + beta[c];
    }
}

// ---------------- launch ----------------
extern "C" void kernel_launch(void* const* d_in, const int* in_sizes, int n_in,
                              void* d_out, int out_size)
{
    const float* x      = (const float*)d_in[0];
    const int*   amask  = (const int*)  d_in[1];
    const float* imp_w1 = (const float*)d_in[2];
    const float* imp_b1 = (const float*)d_in[3];
    const float* imp_g  = (const float*)d_in[4];
    const float* imp_be = (const float*)d_in[5];
    const float* imp_w2 = (const float*)d_in[6];
    const float* imp_b2 = (const float*)d_in[7];
    const float* rsn_w1 = (const float*)d_in[8];
    const float* rsn_b1 = (const float*)d_in[9];
    const float* rsn_g  = (const float*)d_in[10];
    const float* rsn_be = (const float*)d_in[11];
    const float* rsn_w2 = (const float*)d_in[12];
    const float* rsn_b2 = (const float*)d_in[13];
    const float* q_w    = (const float*)d_in[14];
    const float* q_b    = (const float*)d_in[15];
    const float* k_w    = (const float*)d_in[16];
    const float* k_b    = (const float*)d_in[17];
    const float* v_w    = (const float*)d_in[18];
    const float* v_b    = (const float*)d_in[19];
    const float* o_w    = (const float*)d_in[20];
    const float* o_b    = (const float*)d_in[21];
    const float* tmp_w1 = (const float*)d_in[22];
    const float* tmp_b1 = (const float*)d_in[23];
    const float* tmp_g  = (const float*)d_in[24];
    const float* tmp_be = (const float*)d_in[25];
    const float* tmp_w2 = (const float*)d_in[26];
    const float* tmp_b2 = (const float*)d_in[27];
    const float* norm_g = (const float*)d_in[28];
    const float* norm_b = (const float*)d_in[29];
    float* out = (float*)d_out;

    float *Himp, *xi, *Hrsn, *reasoned, *Q, *K, *V, *attn, *proj, *part, *rmean, *temp, *xr;
    float *WtImp, *WtRsn1, *WtRsn2, *WtQ, *WtK, *WtV, *WtO;
    uint32_t* mbits;
    cudaGetSymbolAddress((void**)&Himp,     g_Himp);
    cudaGetSymbolAddress((void**)&xi,       g_xi);
    cudaGetSymbolAddress((void**)&Hrsn,     g_Hrsn);
    cudaGetSymbolAddress((void**)&reasoned, g_reasoned);
    cudaGetSymbolAddress((void**)&Q,        g_Q);
    cudaGetSymbolAddress((void**)&K,        g_K);
    cudaGetSymbolAddress((void**)&V,        g_V);
    cudaGetSymbolAddress((void**)&attn,     g_attn);
    cudaGetSymbolAddress((void**)&proj,     g_proj);
    cudaGetSymbolAddress((void**)&part,     g_part);
    cudaGetSymbolAddress((void**)&rmean,    g_rmean);
    cudaGetSymbolAddress((void**)&temp,     g_temp);
    cudaGetSymbolAddress((void**)&xr,       g_xr);
    cudaGetSymbolAddress((void**)&mbits,    g_mbits);
    cudaGetSymbolAddress((void**)&WtImp,    g_WtImp);
    cudaGetSymbolAddress((void**)&WtRsn1,   g_WtRsn1);
    cudaGetSymbolAddress((void**)&WtRsn2,   g_WtRsn2);
    cudaGetSymbolAddress((void**)&WtQ,      g_WtQ);
    cudaGetSymbolAddress((void**)&WtK,      g_WtK);
    cudaGetSymbolAddress((void**)&WtV,      g_WtV);
    cudaGetSymbolAddress((void**)&WtO,      g_WtO);

    cudaFuncSetAttribute(gemm_tf32, cudaFuncAttributeMaxDynamicSharedMemorySize, GSMEM_BYTES);
    cudaFuncSetAttribute(gemm_tf32_qkv, cudaFuncAttributeMaxDynamicSharedMemorySize, GSMEM_BYTES);
    cudaFuncSetAttribute(flash_wmma_kernel, cudaFuncAttributeMaxDynamicSharedMemorySize, ASM_BYTES);

    // batched weight transposes (+ tf32 rounding)
    TransArgs ta;
    ta.src[0] = imp_w1; ta.dst[0] = WtImp;  ta.n[0] = CH;
    ta.src[1] = rsn_w1; ta.dst[1] = WtRsn1; ta.n[1] = Cz;
    ta.src[2] = rsn_w2; ta.dst[2] = WtRsn2; ta.n[2] = Cz;
    ta.src[3] = q_w;    ta.dst[3] = WtQ;    ta.n[3] = Cz;
    ta.src[4] = k_w;    ta.dst[4] = WtK;    ta.n[4] = Cz;
    ta.src[5] = v_w;    ta.dst[5] = WtV;    ta.n[5] = Cz;
    ta.src[6] = o_w;    ta.dst[6] = WtO;    ta.n[6] = Cz;
    transpose_round_batch<<<dim3(32, 32, 7), dim3(32, 8)>>>(ta);
    round_tf32_kernel<<<NT*Cz/256, 256>>>(x, xr);
    pack_mask_kernel<<<(int)((size_t)Bz*Tz*Tz/256), 256>>>(amask, mbits);

    // 1. importance net first linear
    gemm_tf32<<<dim3(CH/128, NT/128), GT, GSMEM_BYTES>>>(xr, WtImp, imp_b1, Himp, CH, 0);
    // 2. LN + GELU
    ln_gelu_kernel<CH><<<NT, 256>>>(Himp, imp_g, imp_be);
    // 3. gate
    gate_xi_kernel<<<NT, 256>>>(Himp, imp_w2, imp_b2, x, xi);
    // 4. reasoning first linear
    gemm_tf32<<<dim3(Cz/128, NT/128), GT, GSMEM_BYTES>>>(xi, WtRsn1, rsn_b1, Hrsn, Cz, 0);
    // 5. LN + GELU
    ln_gelu_kernel<Cz><<<NT, 256>>>(Hrsn, rsn_g, rsn_be);
    // 6. reasoning second linear (rounded: feeds q-proj)
    gemm_tf32<<<dim3(Cz/128, NT/128), GT, GSMEM_BYTES>>>(Hrsn, WtRsn2, rsn_b2, reasoned, Cz, 1);
    // 7. Q/K/V projections batched (rounded: feed wmma attention)
    gemm_tf32_qkv<<<dim3(Cz/128, NT/128, 3), GT, GSMEM_BYTES>>>(
        reasoned, xi, xr, WtQ, WtK, WtV, q_b, k_b, v_b, Q, K, V);
    // 8. column mean
    colmean_part<<<dim3(Cz/256, Bz, 8), 256>>>(reasoned, part);
    colmean_fin<<<dim3(Cz/256, Bz), 256>>>(part, rmean);
    // 9. temperature net
    temp_kernel<<<Bz, 512>>>(rmean, tmp_w1, tmp_b1, tmp_g, tmp_be, tmp_w2, tmp_b2, temp);
    // 10. attention (wmma tf32)
    flash_wmma_kernel<<<dim3(Tz/128, Hh, Bz), 256, ASM_BYTES>>>(Q, K, V, mbits, temp, attn);
    // 11. output projection
    gemm_tf32<<<dim3(Cz/128, NT/128), GT, GSMEM_BYTES>>>(attn, WtO, o_b, proj, Cz, 0);
    // 12. residual + LN
    resid_ln_kernel<<<NT, 256>>>(x, proj, norm_g, norm_b, out);
}

// round 15
// speedup vs baseline: 1.0184x; 1.0184x over previous
#include <cuda_runtime.h>
#include <cuda_bf16.h>
#include <math.h>
#include <cstdint>
#include <mma.h>

using namespace nvcuda;

// Problem constants
#define Bz 2
#define Tz 2048
#define Cz 1024
#define Hh 16
#define Dd 64
#define CH 512
#define NT (Bz*Tz)          // 4096 rows

// ---------------- scratch (device globals; no runtime alloc) ----------------
__device__ float g_Himp[NT*CH];
__device__ float g_xi[NT*Cz];
__device__ float g_Hrsn[NT*Cz];
__device__ float g_reasoned[NT*Cz];
__device__ float g_Q[NT*Cz];
__device__ float g_K[NT*Cz];
__device__ float g_V[NT*Cz];
__device__ float g_attn[NT*Cz];
__device__ float g_proj[NT*Cz];
__device__ float g_part[16*Cz];
__device__ float g_rmean[Bz*Cz];
__device__ float g_temp[Bz*Hh];
__device__ float g_xr[NT*Cz];          // x rounded to tf32
__device__ uint32_t g_mbits[(size_t)Bz*Tz*Tz/32];   // packed attention mask (1MB)
// transposed (N-major -> [N,K] K-contiguous) + tf32-rounded weights
__device__ float g_WtImp[CH*Cz];
__device__ float g_WtRsn1[Cz*Cz];
__device__ float g_WtRsn2[Cz*Cz];
__device__ float g_WtQ[Cz*Cz];
__device__ float g_WtK[Cz*Cz];
__device__ float g_WtV[Cz*Cz];
__device__ float g_WtO[Cz*Cz];

// ---------------- helpers ----------------
__device__ __forceinline__ uint32_t smem_to_u32(const void* p) {
    uint32_t a;
    asm("{ .reg .u64 t; cvta.to.shared.u64 t, %1; cvt.u32.u64 %0, t; }" : "=r"(a) : "l"(p));
    return a;
}
__device__ __forceinline__ float to_tf32(float f) {
    uint32_t u; asm("cvt.rna.tf32.f32 %0, %1;" : "=r"(u) : "f"(f));
    return __uint_as_float(u);
}
__device__ __forceinline__ void cp_async16(uint32_t dst, const void* src) {
    asm volatile("cp.async.cg.shared.global [%0], [%1], 16;" :: "r"(dst), "l"(src) : "memory");
}
__device__ __forceinline__ void cp_commit() { asm volatile("cp.async.commit_group;" ::: "memory"); }
template<int N> __device__ __forceinline__ void cp_wait() {
    asm volatile("cp.async.wait_group %0;" :: "n"(N) : "memory");
}

__device__ __forceinline__ float blockReduceSum(float v) {
    __shared__ float sh[32];
    int lane = threadIdx.x & 31, wid = threadIdx.x >> 5;
    #pragma unroll
    for (int o = 16; o; o >>= 1) v += __shfl_down_sync(0xffffffffu, v, o);
    if (lane == 0) sh[wid] = v;
    __syncthreads();
    int nw = blockDim.x >> 5;
    v = (threadIdx.x < nw) ? sh[threadIdx.x] : 0.f;
    if (wid == 0) {
        #pragma unroll
        for (int o = 16; o; o >>= 1) v += __shfl_down_sync(0xffffffffu, v, o);
        if (lane == 0) sh[0] = v;
    }
    __syncthreads();
    float r = sh[0];
    __syncthreads();
    return r;
}

__device__ __forceinline__ float gelu_exact(float x) {
    return 0.5f * x * (1.0f + erff(x * 0.70710678118654752f));
}

// ---------------- wmma tf32 GEMM core (4-stage cp.async pipeline, 1 barrier/iter) ----------------
// CTA tile 128x128, 256 threads, 8 warps (2x4), warp tile 64x32 (4x2 frags).
// 4 stages, load kc+3 ahead: write stage (kc+3)%4 is disjoint from read stage kc%4,
// so the post-compute barrier is unnecessary -> ONE __syncthreads per iteration.
#define GLD  36
#define GSTG (128*GLD)
#define GSTAGE_FLOATS (2*GSTG)
#define GNSTAGE 4
#define GSMEM_BYTES (GNSTAGE*GSTAGE_FLOATS*4)    // 147456 B
#define ELD 132

__device__ __forceinline__ void gemm_tf32_body(
    float* smf, uint32_t sb,
    const float* __restrict__ A, const float* __restrict__ Wt,
    const float* __restrict__ bias, float* __restrict__ C,
    int N, int round_out, int bx, int by)
{
    const int tid = threadIdx.x;
    const int wid = tid >> 5;
    const int wm = wid >> 2;          // 0..1
    const int wn = wid & 3;           // 0..3

    wmma::fragment<wmma::accumulator, 16, 16, 8, float> acc[4][2];
    #pragma unroll
    for (int mi = 0; mi < 4; mi++)
        #pragma unroll
        for (int ni = 0; ni < 2; ni++)
            wmma::fill_fragment(acc[mi][ni], 0.0f);

    const float* Abase = A  + (size_t)by * 128 * Cz;
    const float* Bbase = Wt + (size_t)bx * 128 * Cz;

    auto load_stage = [&](int s, int kc) {
        uint32_t ab = sb + (uint32_t)s * GSTAGE_FLOATS * 4;
        uint32_t bb = ab + GSTG * 4;
        #pragma unroll
        for (int i = 0; i < 4; i++) {
            int idx = i * 256 + tid;
            int r = idx >> 3, c = (idx & 7) * 4;
            uint32_t soff = (uint32_t)(r * GLD + c) * 4;
            cp_async16(ab + soff, Abase + (size_t)r * Cz + kc * 32 + c);
            cp_async16(bb + soff, Bbase + (size_t)r * Cz + kc * 32 + c);
        }
        cp_commit();
    };

    load_stage(0, 0);
    load_stage(1, 1);
    load_stage(2, 2);

    for (int kc = 0; kc < 32; kc++) {
        int s = kc & 3;
        if (kc < 30)       cp_wait<2>();
        else if (kc == 30) cp_wait<1>();
        else               cp_wait<0>();
        __syncthreads();   // stage s fully landed across all warps

        // refill: writes stage (kc+3)&3 != s, (kc+1)&3, (kc+2)&3 -> no barrier needed after compute
        if (kc + 3 < 32) load_stage((kc + 3) & 3, kc + 3);

        const float* As = smf + s * GSTAGE_FLOATS;
        const float* Bs = As + GSTG;

        #pragma unroll
        for (int kk = 0; kk < 4; kk++) {
            wmma::fragment<wmma::matrix_a, 16, 16, 8, wmma::precision::tf32, wmma::row_major> af[4];
            wmma::fragment<wmma::matrix_b, 16, 16, 8, wmma::precision::tf32, wmma::col_major> bf[2];
            #pragma unroll
            for (int mi = 0; mi < 4; mi++)
                wmma::load_matrix_sync(af[mi], As + (wm * 64 + mi * 16) * GLD + kk * 8, GLD);
            #pragma unroll
            for (int ni = 0; ni < 2; ni++)
                wmma::load_matrix_sync(bf[ni], Bs + (wn * 32 + ni * 16) * GLD + kk * 8, GLD);
            #pragma unroll
            for (int mi = 0; mi < 4; mi++)
                #pragma unroll
                for (int ni = 0; ni < 2; ni++)
                    wmma::mma_sync(acc[mi][ni], af[mi], bf[ni], acc[mi][ni]);
        }
    }
    // after last barrier (kc=31) all warps compute from stage 3;
    // epilogue smem (67584 B) covers stages 0-1 only -> disjoint, no extra barrier needed
    #pragma unroll
    for (int mi = 0; mi < 4; mi++)
        #pragma unroll
        for (int ni = 0; ni < 2; ni++)
            wmma::store_matrix_sync(smf + (wm * 64 + mi * 16) * ELD + wn * 32 + ni * 16,
                                    acc[mi][ni], ELD, wmma::mem_row_major);
    __syncthreads();

    #pragma unroll
    for (int i = 0; i < 16; i++) {
        int idx = i * 256 + tid;
        int r = idx >> 5, c = (idx & 31) * 4;
        const float* bp = bias + bx * 128 + c;
        float4 o;
        o.x = smf[r * ELD + c + 0] + bp[0];
        o.y = smf[r * ELD + c + 1] + bp[1];
        o.z = smf[r * ELD + c + 2] + bp[2];
        o.w = smf[r * ELD + c + 3] + bp[3];
        if (round_out) {
            o.x = to_tf32(o.x); o.y = to_tf32(o.y);
            o.z = to_tf32(o.z); o.w = to_tf32(o.w);
        }
        *(float4*)&C[(size_t)(by * 128 + r) * N + bx * 128 + c] = o;
    }
}

__global__ __launch_bounds__(256) void gemm_tf32(
    const float* __restrict__ A, const float* __restrict__ Wt,
    const float* __restrict__ bias, float* __restrict__ C,
    int N, int round_out)
{
    extern __shared__ float smf[];
    gemm_tf32_body(smf, smem_to_u32(smf), A, Wt, bias, C, N, round_out,
                   blockIdx.x, blockIdx.y);
}

// batched Q/K/V: blockIdx.z selects (input, weight, bias, output); all N=Cz, rounded
__global__ __launch_bounds__(256) void gemm_tf32_qkv(
    const float* __restrict__ Aq, const float* __restrict__ Ak, const float* __restrict__ Av,
    const float* __restrict__ Wq, const float* __restrict__ Wk, const float* __restrict__ Wv,
    const float* __restrict__ bq, const float* __restrict__ bk, const float* __restrict__ bv,
    float* __restrict__ Cq, float* __restrict__ Ck, float* __restrict__ Cv)
{
    extern __shared__ float smf[];
    const float* A; const float* W; const float* bb; float* C;
    if (blockIdx.z == 0)      { A = Aq; W = Wq; bb = bq; C = Cq; }
    else if (blockIdx.z == 1) { A = Ak; W = Wk; bb = bk; C = Ck; }
    else                      { A = Av; W = Wv; bb = bv; C = Cv; }
    gemm_tf32_body(smf, smem_to_u32(smf), A, W, bb, C, Cz, 1,
                   blockIdx.x, blockIdx.y);
}

// ---------------- batched transpose + round: 7 weights in one launch ----------------
struct TransArgs {
    const float* src[7];
    float* dst[7];
    int n[7];           // N (output rows of Wt); K is always Cz
};

__global__ void transpose_round_batch(TransArgs ta) {
    int z = blockIdx.z;
    int N = ta.n[z];
    int nb = blockIdx.x * 32, kb = blockIdx.y * 32;
    if (nb >= N) return;
    const float* W = ta.src[z];
    float* Wt = ta.dst[z];
    __shared__ float t[32][33];
    #pragma unroll
    for (int i = threadIdx.y; i < 32; i += 8)
        t[i][threadIdx.x] = W[(size_t)(kb + i) * N + nb + threadIdx.x];
    __syncthreads();
    #pragma unroll
    for (int i = threadIdx.y; i < 32; i += 8)
        Wt[(size_t)(nb + i) * Cz + kb + threadIdx.x] = to_tf32(t[threadIdx.x][i]);
}

__global__ void round_tf32_kernel(const float* __restrict__ in, float* __restrict__ out) {
    int i = blockIdx.x * 256 + threadIdx.x;
    out[i] = to_tf32(in[i]);
}

// ---------------- pack mask to bits (ballot) ----------------
__global__ void pack_mask_kernel(const int* __restrict__ mask, uint32_t* __restrict__ mbits) {
    size_t p = (size_t)blockIdx.x * 256 + threadIdx.x;
    unsigned bit = (mask[p] != 0) ? 1u : 0u;
    uint32_t w = __ballot_sync(0xffffffffu, bit);
    if ((threadIdx.x & 31) == 0) mbits[p >> 5] = w;
}

// ---------------- LN + GELU ----------------
template<int COLS>
__global__ __launch_bounds__(256) void ln_gelu_kernel(
    float* __restrict__ X, const float* __restrict__ g, const float* __restrict__ beta)
{
    const int row = blockIdx.x;
    float* xr = X + (size_t)row * COLS;
    constexpr int PT = COLS / 256;
    float v[PT];
    float s = 0.f;
    #pragma unroll
    for (int i = 0; i < PT; i++) { v[i] = xr[threadIdx.x + i * 256]; s += v[i]; }
    float mean = blockReduceSum(s) * (1.0f / COLS);
    float s2 = 0.f;
    #pragma unroll
    for (int i = 0; i < PT; i++) { float d = v[i] - mean; s2 += d * d; }
    float var = blockReduceSum(s2) * (1.0f / COLS);
    float rstd = rsqrtf(var + 1e-5f);
    #pragma unroll
    for (int i = 0; i < PT; i++) {
        int c = threadIdx.x + i * 256;
        float y = (v[i] - mean) * rstd * g[c] + beta[c];
        xr[c] = to_tf32(gelu_exact(y));
    }
}

// ---------------- importance gate ----------------
__global__ __launch_bounds__(256) void gate_xi_kernel(
    const float* __restrict__ H, const float* __restrict__ w2, const float* __restrict__ b2,
    const float* __restrict__ x, float* __restrict__ xi)
{
    const int row = blockIdx.x;
    float p = 0.f;
    const float* hr = H + (size_t)row * CH;
    for (int c = threadIdx.x; c < CH; c += 256) p += hr[c] * w2[c];
    float sum = blockReduceSum(p);
    float sg = 1.0f / (1.0f + expf(-(sum + b2[0])));
    float imp = fmaxf(sg, 1e-6f);
    const float* xr = x + (size_t)row * Cz;
    float* xo = xi + (size_t)row * Cz;
    for (int c = threadIdx.x; c < Cz; c += 256) xo[c] = to_tf32(xr[c] * imp);
}

// ---------------- column mean ----------------
__global__ void colmean_part(const float* __restrict__ R, float* __restrict__ part) {
    int c = blockIdx.x * 256 + threadIdx.x;
    int b = blockIdx.y;
    int ch = blockIdx.z;
    float s = 0.f;
    int t0 = ch * 256;
    for (int t = t0; t < t0 + 256; t++)
        s += R[((size_t)(b * Tz + t)) * Cz + c];
    part[(ch * Bz + b) * Cz + c] = s;
}
__global__ void colmean_fin(const float* __restrict__ part, float* __restrict__ out) {
    int c = blockIdx.x * 256 + threadIdx.x;
    int b = blockIdx.y;
    float s = 0.f;
    for (int ch = 0; ch < 8; ch++) s += part[(ch * Bz + b) * Cz + c];
    out[b * Cz + c] = s * (1.0f / Tz);
}

// ---------------- temperature net ----------------
__global__ __launch_bounds__(512) void temp_kernel(
    const float* __restrict__ rmean,
    const float* __restrict__ w1, const float* __restrict__ b1,
    const float* __restrict__ g, const float* __restrict__ beta,
    const float* __restrict__ w2, const float* __restrict__ b2,
    float* __restrict__ temp)
{
    const int b = blockIdx.x;
    const int tid = threadIdx.x;
    __shared__ float hsm[CH];
    const float* xr = rmean + b * Cz;
    float acc = b1[tid];
    for (int k = 0; k < Cz; k++) acc = fmaf(xr[k], w1[k * CH + tid], acc);
    float mean = blockReduceSum(acc) * (1.0f / CH);
    float d = acc - mean;
    float var = blockReduceSum(d * d) * (1.0f / CH);
    float rstd = rsqrtf(var + 1e-5f);
    float y = d * rstd * g[tid] + beta[tid];
    hsm[tid] = gelu_exact(y);
    __syncthreads();
    if (tid < Hh) {
        float a2 = b2[tid];
        for (int k = 0; k < CH; k++) a2 = fmaf(hsm[k], w2[k * Hh + tid], a2);
        float sp = (a2 > 20.f) ? a2 : log1pf(expf(a2));
        temp[b * Hh + tid] = sp + 0.5f;
    }
}

// ---------------- wmma tf32 flash attention ----------------
#define AQS 0
#define AKS 8704
#define AVS 17408
#define ASS 25600
#define AOS 42496
#define AMS 51200
#define ALS 51328
#define ACS 51456
#define ASM_FLOATS 51584
#define ASM_BYTES (ASM_FLOATS*4)

__global__ __launch_bounds__(256) void flash_wmma_kernel(
    const float* __restrict__ Q, const float* __restrict__ Kp,
    const float* __restrict__ Vp, const uint32_t* __restrict__ mbits,
    const float* __restrict__ temp, float* __restrict__ O)
{
    extern __shared__ float smf[];
    uint32_t sb = smem_to_u32(smf);
    const int tid = threadIdx.x;
    const int wid = tid >> 5;
    const int wm = wid >> 2;          // 0..1
    const int wn = wid & 3;           // 0..3
    const int qt = blockIdx.x, h = blockIdx.y, b = blockIdx.z;
    const int qrow0 = qt * 128;
    const float sc = 0.125f * temp[b * Hh + h];

    #pragma unroll
    for (int i = 0; i < 8; i++) {
        int idx = i * 256 + tid;
        int r = idx >> 4, c4 = (idx & 15) * 4;
        float4 qv = *(const float4*)(Q + ((size_t)(b * Tz + qrow0 + r)) * Cz + h * Dd + c4);
        *(float4*)&smf[AQS + r * 68 + c4] = qv;
    }
    if (tid < 128) { smf[AMS + tid] = -1e30f; smf[ALS + tid] = 0.f; }

    auto load_K = [&](int k0) {
        #pragma unroll
        for (int i = 0; i < 8; i++) {
            int idx = i * 256 + tid;
            int r = idx >> 4, c4 = (idx & 15) * 4;
            cp_async16(sb + (AKS + r * 68 + c4) * 4,
                       Kp + ((size_t)(b * Tz + k0 + r)) * Cz + h * Dd + c4);
        }
        cp_commit();
    };
    auto load_V = [&](int k0) {
        #pragma unroll
        for (int i = 0; i < 8; i++) {
            int idx = i * 256 + tid;
            int r = idx >> 4, c4 = (idx & 15) * 4;
            cp_async16(sb + (AVS + r * 64 + c4) * 4,
                       Vp + ((size_t)(b * Tz + k0 + r)) * Cz + h * Dd + c4);
        }
        cp_commit();
    };

    load_K(0);
    load_V(0);
    __syncthreads();

    const int NBLK = Tz / 128;   // 16
    for (int blk = 0; blk < NBLK; blk++) {
        int k0 = blk * 128;
        cp_wait<1>();
        __syncthreads();

        // ---- S = Q @ K^T ----
        {
            wmma::fragment<wmma::accumulator, 16, 16, 8, float> acc[4][2];
            #pragma unroll
            for (int mi = 0; mi < 4; mi++)
                #pragma unroll
                for (int ni = 0; ni < 2; ni++)
                    wmma::fill_fragment(acc[mi][ni], 0.0f);
            #pragma unroll
            for (int kk = 0; kk < 8; kk++) {
                wmma::fragment<wmma::matrix_a, 16, 16, 8, wmma::precision::tf32, wmma::row_major> af[4];
                wmma::fragment<wmma::matrix_b, 16, 16, 8, wmma::precision::tf32, wmma::col_major> bf[2];
                #pragma unroll
                for (int mi = 0; mi < 4; mi++)
                    wmma::load_matrix_sync(af[mi], smf + AQS + (wm * 64 + mi * 16) * 68 + kk * 8, 68);
                #pragma unroll
                for (int ni = 0; ni < 2; ni++)
                    wmma::load_matrix_sync(bf[ni], smf + AKS + (wn * 32 + ni * 16) * 68 + kk * 8, 68);
                #pragma unroll
                for (int mi = 0; mi < 4; mi++)
                    #pragma unroll
                    for (int ni = 0; ni < 2; ni++)
                        wmma::mma_sync(acc[mi][ni], af[mi], bf[ni], acc[mi][ni]);
            }
            #pragma unroll
            for (int mi = 0; mi < 4; mi++)
                #pragma unroll
                for (int ni = 0; ni < 2; ni++)
                    wmma::store_matrix_sync(smf + ASS + (wm * 64 + mi * 16) * 132 + wn * 32 + ni * 16,
                                            acc[mi][ni], 132, wmma::mem_row_major);
        }
        __syncthreads();

        if (blk + 1 < NBLK) load_K(k0 + 128);

        // ---- online softmax ----
        {
            int r = tid >> 1, c0 = (tid & 1) * 64;
            size_t mb_idx = (((size_t)(b * Tz + qrow0 + r)) * Tz + k0 + c0) >> 5;
            uint32_t w0 = mbits[mb_idx], w1 = mbits[mb_idx + 1];
            uint64_t mw = (uint64_t)w0 | ((uint64_t)w1 << 32);
            float* Srow = smf + ASS + r * 132 + c0;
            float vmax = -1e30f;
            #pragma unroll
            for (int j = 0; j < 64; j++) {
                float s = Srow[j];
                s = ((mw >> j) & 1ull) ? s * sc : -1e30f;
                Srow[j] = s;
                vmax = fmaxf(vmax, s);
            }
            vmax = fmaxf(vmax, __shfl_xor_sync(0xffffffffu, vmax, 1));
            float mold = smf[AMS + r];
            float mnew = fmaxf(mold, vmax);
            float corr = __expf(mold - mnew);
            float lsum = 0.f;
            #pragma unroll
            for (int j = 0; j < 64; j++) {
                float p = __expf(Srow[j] - mnew);
                lsum += p;
                Srow[j] = to_tf32(p);
            }
            lsum += __shfl_xor_sync(0xffffffffu, lsum, 1);
            if ((tid & 1) == 0) {
                smf[AMS + r] = mnew;
                smf[ALS + r] = smf[ALS + r] * corr + lsum;
                smf[ACS + r] = corr;
            }
        }

        if (blk + 1 < NBLK) cp_wait<1>(); else cp_wait<0>();
        __syncthreads();

        // ---- PV = P @ V ----
        {
            wmma::fragment<wmma::accumulator, 16, 16, 8, float> acc2[4];
            #pragma unroll
            for (int mi = 0; mi < 4; mi++) wmma::fill_fragment(acc2[mi], 0.0f);
            #pragma unroll
            for (int kk = 0; kk < 16; kk++) {
                wmma::fragment<wmma::matrix_b, 16, 16, 8, wmma::precision::tf32, wmma::row_major> bf;
                wmma::load_matrix_sync(bf, smf + AVS + (kk * 8) * 64 + wn * 16, 64);
                #pragma unroll
                for (int mi = 0; mi < 4; mi++) {
                    wmma::fragment<wmma::matrix_a, 16, 16, 8, wmma::precision::tf32, wmma::row_major> af;
                    wmma::load_matrix_sync(af, smf + ASS + (wm * 64 + mi * 16) * 132 + kk * 8, 132);
                    wmma::mma_sync(acc2[mi], af, bf, acc2[mi]);
                }
            }
            __syncthreads();
            #pragma unroll
            for (int mi = 0; mi < 4; mi++)
                wmma::store_matrix_sync(smf + ASS + (wm * 64 + mi * 16) * 132 + wn * 16,
                                        acc2[mi], 132, wmma::mem_row_major);
        }

        if (blk + 1 < NBLK) load_V(k0 + 128);
        __syncthreads();

        // ---- merge into O ----
        if (blk == 0) {
            #pragma unroll
            for (int i = 0; i < 32; i++) {
                int idx = i * 256 + tid;
                int r = idx >> 6, c = idx & 63;
                smf[AOS + r * 68 + c] = smf[ASS + r * 132 + c];
            }
        } else {
            #pragma unroll
            for (int i = 0; i < 32; i++) {
                int idx = i * 256 + tid;
                int r = idx >> 6, c = idx & 63;
                smf[AOS + r * 68 + c] = smf[AOS + r * 68 + c] * smf[ACS + r] + smf[ASS + r * 132 + c];
            }
        }
        __syncthreads();
    }

    #pragma unroll
    for (int i = 0; i < 32; i++) {
        int idx = i * 256 + tid;
        int r = idx >> 6, c = idx & 63;
        float val = smf[AOS + r * 68 + c] / smf[ALS + r];
        O[((size_t)(b * Tz + qrow0 + r)) * Cz + h * Dd + c] = to_tf32(val);
    }
}

// ---------------- residual + LayerNorm epilogue ----------------
__global__ __launch_bounds__(256) void resid_ln_kernel(
    const float* __restrict__ x, const float* __restrict__ p,
    const float* __restrict__ g, const float* __restrict__ beta,
    float* __restrict__ out)
{
    const int row = blockIdx.x;
    const float* xr = x + (size_t)row * Cz;
    const float* pr = p + (size_t)row * Cz;
    float v[4];
    float s = 0.f;
    #pragma unroll
    for (int i = 0; i < 4; i++) {
        int c = threadIdx.x + i * 256;
        v[i] = xr[c] + pr[c];
        s += v[i];
    }
    float mean = blockReduceSum(s) * (1.0f / Cz);
    float s2 = 0.f;
    #pragma unroll
    for (int i = 0; i < 4; i++) { float d = v[i] - mean; s2 += d * d; }
    float var = blockReduceSum(s2) * (1.0f / Cz);
    float rstd = rsqrtf(var + 1e-5f);
    #pragma unroll
    for (int i = 0; i < 4; i++) {
        int c = threadIdx.x + i * 256;
        out[(size_t)row * Cz + c] = (v[i] - mean) * rstd * g[c] + beta[c];
    }
}

// ---------------- launch ----------------
extern "C" void kernel_launch(void* const* d_in, const int* in_sizes, int n_in,
                              void* d_out, int out_size)
{
    const float* x      = (const float*)d_in[0];
    const int*   amask  = (const int*)  d_in[1];
    const float* imp_w1 = (const float*)d_in[2];
    const float* imp_b1 = (const float*)d_in[3];
    const float* imp_g  = (const float*)d_in[4];
    const float* imp_be = (const float*)d_in[5];
    const float* imp_w2 = (const float*)d_in[6];
    const float* imp_b2 = (const float*)d_in[7];
    const float* rsn_w1 = (const float*)d_in[8];
    const float* rsn_b1 = (const float*)d_in[9];
    const float* rsn_g  = (const float*)d_in[10];
    const float* rsn_be = (const float*)d_in[11];
    const float* rsn_w2 = (const float*)d_in[12];
    const float* rsn_b2 = (const float*)d_in[13];
    const float* q_w    = (const float*)d_in[14];
    const float* q_b    = (const float*)d_in[15];
    const float* k_w    = (const float*)d_in[16];
    const float* k_b    = (const float*)d_in[17];
    const float* v_w    = (const float*)d_in[18];
    const float* v_b    = (const float*)d_in[19];
    const float* o_w    = (const float*)d_in[20];
    const float* o_b    = (const float*)d_in[21];
    const float* tmp_w1 = (const float*)d_in[22];
    const float* tmp_b1 = (const float*)d_in[23];
    const float* tmp_g  = (const float*)d_in[24];
    const float* tmp_be = (const float*)d_in[25];
    const float* tmp_w2 = (const float*)d_in[26];
    const float* tmp_b2 = (const float*)d_in[27];
    const float* norm_g = (const float*)d_in[28];
    const float* norm_b = (const float*)d_in[29];
    float* out = (float*)d_out;

    float *Himp, *xi, *Hrsn, *reasoned, *Q, *K, *V, *attn, *proj, *part, *rmean, *temp, *xr;
    float *WtImp, *WtRsn1, *WtRsn2, *WtQ, *WtK, *WtV, *WtO;
    uint32_t* mbits;
    cudaGetSymbolAddress((void**)&Himp,     g_Himp);
    cudaGetSymbolAddress((void**)&xi,       g_xi);
    cudaGetSymbolAddress((void**)&Hrsn,     g_Hrsn);
    cudaGetSymbolAddress((void**)&reasoned, g_reasoned);
    cudaGetSymbolAddress((void**)&Q,        g_Q);
    cudaGetSymbolAddress((void**)&K,        g_K);
    cudaGetSymbolAddress((void**)&V,        g_V);
    cudaGetSymbolAddress((void**)&attn,     g_attn);
    cudaGetSymbolAddress((void**)&proj,     g_proj);
    cudaGetSymbolAddress((void**)&part,     g_part);
    cudaGetSymbolAddress((void**)&rmean,    g_rmean);
    cudaGetSymbolAddress((void**)&temp,     g_temp);
    cudaGetSymbolAddress((void**)&xr,       g_xr);
    cudaGetSymbolAddress((void**)&mbits,    g_mbits);
    cudaGetSymbolAddress((void**)&WtImp,    g_WtImp);
    cudaGetSymbolAddress((void**)&WtRsn1,   g_WtRsn1);
    cudaGetSymbolAddress((void**)&WtRsn2,   g_WtRsn2);
    cudaGetSymbolAddress((void**)&WtQ,      g_WtQ);
    cudaGetSymbolAddress((void**)&WtK,      g_WtK);
    cudaGetSymbolAddress((void**)&WtV,      g_WtV);
    cudaGetSymbolAddress((void**)&WtO,      g_WtO);

    cudaFuncSetAttribute(gemm_tf32, cudaFuncAttributeMaxDynamicSharedMemorySize, GSMEM_BYTES);
    cudaFuncSetAttribute(gemm_tf32_qkv, cudaFuncAttributeMaxDynamicSharedMemorySize, GSMEM_BYTES);
    cudaFuncSetAttribute(flash_wmma_kernel, cudaFuncAttributeMaxDynamicSharedMemorySize, ASM_BYTES);

    // batched weight transposes (+ tf32 rounding)
    TransArgs ta;
    ta.src[0] = imp_w1; ta.dst[0] = WtImp;  ta.n[0] = CH;
    ta.src[1] = rsn_w1; ta.dst[1] = WtRsn1; ta.n[1] = Cz;
    ta.src[2] = rsn_w2; ta.dst[2] = WtRsn2; ta.n[2] = Cz;
    ta.src[3] = q_w;    ta.dst[3] = WtQ;    ta.n[3] = Cz;
    ta.src[4] = k_w;    ta.dst[4] = WtK;    ta.n[4] = Cz;
    ta.src[5] = v_w;    ta.dst[5] = WtV;    ta.n[5] = Cz;
    ta.src[6] = o_w;    ta.dst[6] = WtO;    ta.n[6] = Cz;
    transpose_round_batch<<<dim3(32, 32, 7), dim3(32, 8)>>>(ta);
    round_tf32_kernel<<<NT*Cz/256, 256>>>(x, xr);
    pack_mask_kernel<<<(int)((size_t)Bz*Tz*Tz/256), 256>>>(amask, mbits);

    // 1. importance net first linear
    gemm_tf32<<<dim3(CH/128, NT/128), 256, GSMEM_BYTES>>>(xr, WtImp, imp_b1, Himp, CH, 0);
    // 2. LN + GELU
    ln_gelu_kernel<CH><<<NT, 256>>>(Himp, imp_g, imp_be);
    // 3. gate
    gate_xi_kernel<<<NT, 256>>>(Himp, imp_w2, imp_b2, x, xi);
    // 4. reasoning first linear
    gemm_tf32<<<dim3(Cz/128, NT/128), 256, GSMEM_BYTES>>>(xi, WtRsn1, rsn_b1, Hrsn, Cz, 0);
    // 5. LN + GELU
    ln_gelu_kernel<Cz><<<NT, 256>>>(Hrsn, rsn_g, rsn_be);
    // 6. reasoning second linear (rounded: feeds q-proj)
    gemm_tf32<<<dim3(Cz/128, NT/128), 256, GSMEM_BYTES>>>(Hrsn, WtRsn2, rsn_b2, reasoned, Cz, 1);
    // 7. Q/K/V projections batched (rounded: feed wmma attention)
    gemm_tf32_qkv<<<dim3(Cz/128, NT/128, 3), 256, GSMEM_BYTES>>>(
        reasoned, xi, xr, WtQ, WtK, WtV, q_b, k_b, v_b, Q, K, V);
    // 8. column mean
    colmean_part<<<dim3(Cz/256, Bz, 8), 256>>>(reasoned, part);
    colmean_fin<<<dim3(Cz/256, Bz), 256>>>(part, rmean);
    // 9. temperature net
    temp_kernel<<<Bz, 512>>>(rmean, tmp_w1, tmp_b1, tmp_g, tmp_be, tmp_w2, tmp_b2, temp);
    // 10. attention (wmma tf32)
    flash_wmma_kernel<<<dim3(Tz/128, Hh, Bz), 256, ASM_BYTES>>>(Q, K, V, mbits, temp, attn);
    // 11. output projection
    gemm_tf32<<<dim3(Cz/128, NT/128), 256, GSMEM_BYTES>>>(attn, WtO, o_b, proj, Cz, 0);
    // 12. residual + LN
    resid_ln_kernel<<<NT, 256>>>(x, proj, norm_g, norm_b, out);
}